// round 2
// baseline (speedup 1.0000x reference)
#include <cuda_runtime.h>
#include <math.h>

#define H_ 96
#define W_ 128
#define C_ 21
#define N_ (H_*W_)
#define TX 16

// Scratch (allocation-free rule: __device__ globals)
__device__ float g_p[C_*N_];     // softmax probabilities, channel-major [C][N]
__device__ float g_tmp[C_*N_];   // after horizontal conv
__device__ float g_s[C_*N_];     // after vertical conv (spatial_out * norm)
__device__ float g_kx[W_];
__device__ float g_ky[H_];
__device__ float g_nx[W_];
__device__ float g_ny[H_];
__device__ float g_A[C_*C_];     // compat @ (Ws + Wb)

// One block, 512 threads: 1D Gaussian taps, row/col normalizers, fused 21x21 matrix.
__global__ void init_kernel(const float* __restrict__ ws,
                            const float* __restrict__ wb,
                            const float* __restrict__ compat) {
    int t = threadIdx.x;
    if (t < W_) g_kx[t] = expf(-(float)(t*t) / 18.0f);   // exp(-0.5*(d/3)^2)
    if (t < H_) g_ky[t] = expf(-(float)(t*t) / 18.0f);
    __syncthreads();
    if (t < W_) {
        float s = 0.f;
        for (int x = 0; x < W_; x++) s += g_kx[abs(t - x)];
        g_nx[t] = s;
    }
    if (t < H_) {
        float s = 0.f;
        for (int y = 0; y < H_; y++) s += g_ky[abs(t - y)];
        g_ny[t] = s;
    }
    if (t < C_*C_) {
        int i = t / C_, j = t % C_;
        float a = 0.f;
        #pragma unroll
        for (int k = 0; k < C_; k++)
            a += compat[i*C_ + k] * (ws[k*C_ + j] + wb[k*C_ + j]);
        g_A[t] = a;
    }
}

// p0 = softmax(unaries) over channels; unaries is NHWC -> read [n*C + c]
__global__ void softmax0_kernel(const float* __restrict__ un) {
    int n = blockIdx.x * blockDim.x + threadIdx.x;
    if (n >= N_) return;
    float v[C_];
    float m = -1e30f;
    #pragma unroll
    for (int c = 0; c < C_; c++) { v[c] = un[n*C_ + c]; m = fmaxf(m, v[c]); }
    float s = 0.f;
    #pragma unroll
    for (int c = 0; c < C_; c++) { v[c] = expf(v[c] - m); s += v[c]; }
    float inv = 1.0f / s;
    #pragma unroll
    for (int c = 0; c < C_; c++) g_p[c*N_ + n] = v[c] * inv;
}

// Horizontal (x) conv: block = one (class, row); 128 threads
__global__ void hconv_kernel() {
    __shared__ float row[W_];
    __shared__ float kx[W_];
    int c = blockIdx.x / H_;
    int y = blockIdx.x % H_;
    int x = threadIdx.x;
    row[x] = g_p[c*N_ + y*W_ + x];
    kx[x]  = g_kx[x];
    __syncthreads();
    float acc = 0.f;
    #pragma unroll 8
    for (int xp = 0; xp < W_; xp++) acc += kx[abs(x - xp)] * row[xp];
    g_tmp[c*N_ + y*W_ + x] = acc;
}

// Vertical (y) conv: block = one (class, 16-wide x tile); 16x16 threads
__global__ void vconv_kernel() {
    __shared__ float col[H_*TX];
    __shared__ float ky[H_];
    int c  = blockIdx.x / (W_/TX);
    int x0 = (blockIdx.x % (W_/TX)) * TX;
    int tx = threadIdx.x;   // 0..15
    int ty = threadIdx.y;   // 0..15
    int tid = ty*TX + tx;
    for (int y = ty; y < H_; y += 16)
        col[y*TX + tx] = g_tmp[c*N_ + y*W_ + x0 + tx];
    if (tid < H_) ky[tid] = g_ky[tid];
    __syncthreads();
    for (int y = ty; y < H_; y += 16) {
        float acc = 0.f;
        #pragma unroll 8
        for (int yp = 0; yp < H_; yp++) acc += ky[abs(y - yp)] * col[yp*TX + tx];
        g_s[c*N_ + y*W_ + x0 + tx] = acc;
    }
}

// Fused: q = u - A @ (s / norm); then softmax->p (iters 0..3)
// or write final q to d_out in (1, W, H, C) layout (iter 4).
__global__ void update_kernel(const float* __restrict__ un, int last,
                              float* __restrict__ out) {
    __shared__ float A[C_*C_];
    for (int t = threadIdx.x; t < C_*C_; t += blockDim.x) A[t] = g_A[t];
    __syncthreads();
    int n = blockIdx.x * blockDim.x + threadIdx.x;
    if (n >= N_) return;
    int y = n / W_, x = n % W_;
    float inv = 1.0f / (g_nx[x] * g_ny[y]);
    float sv[C_];
    #pragma unroll
    for (int c = 0; c < C_; c++) sv[c] = g_s[c*N_ + n] * inv;
    float q[C_];
    #pragma unroll
    for (int c = 0; c < C_; c++) {
        float acc = 0.f;
        #pragma unroll
        for (int cp = 0; cp < C_; cp++) acc += A[c*C_ + cp] * sv[cp];
        q[c] = un[n*C_ + c] - acc;
    }
    if (last) {
        float* o = out + (x*H_ + y)*C_;   // out[0, w, h, c] = q[c, h, w]
        #pragma unroll
        for (int c = 0; c < C_; c++) o[c] = q[c];
    } else {
        float m = -1e30f;
        #pragma unroll
        for (int c = 0; c < C_; c++) m = fmaxf(m, q[c]);
        float s = 0.f;
        #pragma unroll
        for (int c = 0; c < C_; c++) { q[c] = expf(q[c] - m); s += q[c]; }
        float is = 1.0f / s;
        #pragma unroll
        for (int c = 0; c < C_; c++) g_p[c*N_ + n] = q[c] * is;
    }
}

extern "C" void kernel_launch(void* const* d_in, const int* in_sizes, int n_in,
                              void* d_out, int out_size) {
    const float* un     = (const float*)d_in[0];
    // d_in[1] = rgb : provably unused (bilateral output is discarded by the
    // replicated source bug; the message uses spatial_out for both terms)
    const float* ws     = (const float*)d_in[2];
    const float* wb     = (const float*)d_in[3];
    const float* compat = (const float*)d_in[4];
    float* out = (float*)d_out;

    init_kernel<<<1, 512>>>(ws, wb, compat);
    softmax0_kernel<<<(N_ + 255)/256, 256>>>(un);
    for (int it = 0; it < 5; it++) {
        hconv_kernel<<<C_*H_, W_>>>();
        vconv_kernel<<<C_*(W_/TX), dim3(TX, 16)>>>();
        update_kernel<<<(N_ + 255)/256, 256>>>(un, it == 4, out);
    }
}

// round 3
// speedup vs baseline: 2.0468x; 2.0468x over previous
#include <cuda_runtime.h>
#include <math.h>

#define H_   96
#define W_   128
#define C_   21
#define N_   (H_*W_)
#define RAD  16
#define TAPS 33
#define GRID 148
#define NTHR 256
#define PPW  (W_ + 2*RAD)   // 160 padded row width

// Scratch (__device__ globals: allocation-free rule)
__device__ float g_tmp[C_*N_];   // after horizontal conv
__device__ float g_s[C_*N_];     // after vertical conv
__device__ unsigned g_bar_arrive;
__device__ unsigned g_bar_gen;

// Sense-reversing grid barrier. Safe: grid==148 <= SM count, 1 CTA/SM resident.
__device__ __forceinline__ void grid_bar() {
    __syncthreads();
    if (threadIdx.x == 0) {
        __threadfence();
        unsigned gen = atomicAdd(&g_bar_gen, 0u);
        if (atomicAdd(&g_bar_arrive, 1u) == GRID - 1) {
            atomicExch(&g_bar_arrive, 0u);
            __threadfence();
            atomicAdd(&g_bar_gen, 1u);
        } else {
            while (atomicAdd(&g_bar_gen, 0u) == gen) __nanosleep(40);
        }
        __threadfence();
    }
    __syncthreads();
}

// Fused update + softmax + horizontal conv for one image row (block = row y).
// first==true: q = unaries (initial softmax). Writes g_tmp.
__device__ __forceinline__ void ush_stage(
    const float* __restrict__ un, const float* sA, const float* skx,
    const float* sinx, const float* siny, float* sbuf,
    int bid, int t, bool first)
{
    if (bid >= H_) return;
    const int y = bid;
    float* sv = sbuf;            // [C_][W_]
    float* pp = sbuf + C_*W_;    // [C_][PPW] padded softmax rows

    if (!first) {
        #pragma unroll
        for (int r = 0; r < 11; r++) {
            int idx = t + r*NTHR;
            if (idx < C_*W_) {
                int c = idx >> 7, x = idx & 127;
                sv[idx] = __ldcv(&g_s[c*N_ + y*W_ + x]) * (sinx[x] * siny[y]);
            }
        }
    }
    // zero the conv pads
    #pragma unroll
    for (int r = 0; r < 3; r++) {
        int idx = t + r*NTHR;
        if (idx < C_*2*RAD) {
            int c = idx / (2*RAD), k = idx % (2*RAD);
            pp[c*PPW + (k < RAD ? k : W_ + k)] = 0.f;
        }
    }
    __syncthreads();

    if (t < W_) {
        const int x = t;
        float q[C_];
        #pragma unroll
        for (int c = 0; c < C_; c++) q[c] = un[(y*W_ + x)*C_ + c];
        if (!first) {
            #pragma unroll
            for (int cp = 0; cp < C_; cp++) {
                float s = sv[cp*W_ + x];
                #pragma unroll
                for (int c = 0; c < C_; c++) q[c] -= sA[c*C_ + cp] * s;  // 21 indep accs
            }
        }
        float m = q[0];
        #pragma unroll
        for (int c = 1; c < C_; c++) m = fmaxf(m, q[c]);
        float sum = 0.f;
        #pragma unroll
        for (int c = 0; c < C_; c++) { q[c] = expf(q[c] - m); sum += q[c]; }
        float inv = 1.0f / sum;
        #pragma unroll
        for (int c = 0; c < C_; c++) pp[c*PPW + RAD + x] = q[c] * inv;
    }
    __syncthreads();

    // horizontal 33-tap conv, 11-way unrolled independent chains
    #pragma unroll
    for (int r = 0; r < 11; r++) {
        int idx = t + r*NTHR;
        if (idx < C_*W_) {
            int c = idx >> 7, x = idx & 127;
            const float* p = pp + c*PPW + x;
            float acc = 0.f;
            #pragma unroll
            for (int j = 0; j < TAPS; j++) acc += skx[j] * p[j];
            g_tmp[c*N_ + y*W_ + x] = acc;
        }
    }
}

// Vertical conv: unit = (class, 8-wide x tile); 336 units striped over 148 blocks.
__device__ __forceinline__ void vstage(const float* skx, float* sbuf, int bid, int t)
{
    for (int u = bid; u < C_*(W_/8); u += GRID) {
        int c  = u >> 4;
        int x0 = (u & 15) << 3;
        #pragma unroll
        for (int r = 0; r < 4; r++) {           // load 128 padded rows x 8 cols
            int idx = t + r*NTHR;
            int yy = idx >> 3, xx = idx & 7;
            int yv = yy - RAD;
            sbuf[idx] = (yv >= 0 && yv < H_) ? __ldcv(&g_tmp[c*N_ + yv*W_ + x0 + xx]) : 0.f;
        }
        __syncthreads();
        #pragma unroll
        for (int r = 0; r < 3; r++) {           // 768 outputs
            int idx = t + r*NTHR;
            int yv = idx >> 3, xx = idx & 7;
            float acc = 0.f;
            #pragma unroll
            for (int j = 0; j < TAPS; j++) acc += skx[j] * sbuf[(yv + j)*8 + xx];
            g_s[c*N_ + yv*W_ + x0 + xx] = acc;
        }
        __syncthreads();
    }
}

// Final update: q = u - A*(s/norm), write out in (1, W, H, C) layout.
__device__ __forceinline__ void final_stage(
    const float* __restrict__ un, float* __restrict__ out,
    const float* sA, const float* sinx, const float* siny,
    float* sbuf, int bid, int t)
{
    if (bid >= H_) return;
    const int y = bid;
    float* sv = sbuf;
    #pragma unroll
    for (int r = 0; r < 11; r++) {
        int idx = t + r*NTHR;
        if (idx < C_*W_) {
            int c = idx >> 7, x = idx & 127;
            sv[idx] = __ldcv(&g_s[c*N_ + y*W_ + x]) * (sinx[x] * siny[y]);
        }
    }
    __syncthreads();
    if (t < W_) {
        const int x = t;
        float q[C_];
        #pragma unroll
        for (int c = 0; c < C_; c++) q[c] = un[(y*W_ + x)*C_ + c];
        #pragma unroll
        for (int cp = 0; cp < C_; cp++) {
            float s = sv[cp*W_ + x];
            #pragma unroll
            for (int c = 0; c < C_; c++) q[c] -= sA[c*C_ + cp] * s;
        }
        float* o = out + (x*H_ + y)*C_;   // out[0, w, h, c]
        #pragma unroll
        for (int c = 0; c < C_; c++) o[c] = q[c];
    }
}

__global__ __launch_bounds__(NTHR, 1)
void crf_persistent(const float* __restrict__ un,
                    const float* __restrict__ ws,
                    const float* __restrict__ wb,
                    const float* __restrict__ compat,
                    float* __restrict__ out)
{
    __shared__ float sA[C_*C_];
    __shared__ float skx[TAPS];
    __shared__ float sinx[W_];
    __shared__ float siny[H_];
    __shared__ float sbuf[C_*W_ + C_*PPW];   // 2688 + 3360 floats

    const int t   = threadIdx.x;
    const int bid = blockIdx.x;

    // ---- per-block init (redundant across blocks; trivially cheap) ----
    if (t < TAPS) skx[t] = expf(-(float)((t-RAD)*(t-RAD)) / 18.0f);
    __syncthreads();
    if (t < W_) {
        float s = 0.f;
        #pragma unroll
        for (int j = 0; j < TAPS; j++) {
            int xp = t + j - RAD;
            if (xp >= 0 && xp < W_) s += skx[j];
        }
        sinx[t] = 1.0f / s;
    }
    if (t >= 128 && t < 128 + H_) {
        int y = t - 128;
        float s = 0.f;
        #pragma unroll
        for (int j = 0; j < TAPS; j++) {
            int yp = y + j - RAD;
            if (yp >= 0 && yp < H_) s += skx[j];
        }
        siny[y] = 1.0f / s;
    }
    for (int idx = t; idx < C_*C_; idx += NTHR) {
        int i = idx / C_, j = idx % C_;
        float a = 0.f;
        #pragma unroll
        for (int k = 0; k < C_; k++)
            a += compat[i*C_ + k] * (ws[k*C_ + j] + wb[k*C_ + j]);
        sA[idx] = a;   // A = compat @ (Ws + Wb); bilateral path is dead code (source bug)
    }
    __syncthreads();

    // iter 0 front half: softmax(u) + hconv
    ush_stage(un, sA, skx, sinx, siny, sbuf, bid, t, true);
    grid_bar();
    for (int it = 0; it < 5; it++) {
        vstage(skx, sbuf, bid, t);
        grid_bar();
        if (it < 4) {
            ush_stage(un, sA, skx, sinx, siny, sbuf, bid, t, false);
            grid_bar();
        } else {
            final_stage(un, out, sA, sinx, siny, sbuf, bid, t);
        }
    }
}

extern "C" void kernel_launch(void* const* d_in, const int* in_sizes, int n_in,
                              void* d_out, int out_size) {
    const float* un     = (const float*)d_in[0];
    // d_in[1] = rgb : provably unused (bilateral output discarded by replicated source bug)
    const float* ws     = (const float*)d_in[2];
    const float* wb     = (const float*)d_in[3];
    const float* compat = (const float*)d_in[4];
    float* out = (float*)d_out;

    crf_persistent<<<GRID, NTHR>>>(un, ws, wb, compat, out);
}

// round 4
// speedup vs baseline: 2.4320x; 1.1882x over previous
#include <cuda_runtime.h>
#include <math.h>

#define H_   96
#define W_   128
#define C_   21
#define N_   (H_*W_)
#define RAD  16
#define TAPS 33
#define GRID 148
#define NTHR 512
#define PPW  168            // padded row stride for hconv (needs >= 164)

// Scratch (__device__ globals: allocation-free rule)
__device__ float g_tmp[C_*N_];           // after horizontal conv
__device__ float g_s[C_*N_];             // after vertical conv
__device__ unsigned g_bar_arrive;
__device__ volatile unsigned g_bar_gen;

// Sense-reversing grid barrier. Safe: GRID=148 <= SM count, 1 CTA/SM resident.
__device__ __forceinline__ void grid_bar() {
    __syncthreads();
    if (threadIdx.x == 0) {
        __threadfence();
        unsigned gen = g_bar_gen;
        if (atomicAdd(&g_bar_arrive, 1u) == GRID - 1) {
            g_bar_arrive = 0u;
            __threadfence();
            g_bar_gen = gen + 1u;
        } else {
            while (g_bar_gen == gen) __nanosleep(20);
        }
        __threadfence();
    }
    __syncthreads();
}

// channel split over 4 thread groups: sizes 6,5,5,5
__device__ __forceinline__ int grp_c0(int g)  { return (g == 0) ? 0 : (1 + 5*g); }
__device__ __forceinline__ int grp_len(int g) { return (g == 0) ? 6 : 5; }

// Fused update + softmax + horizontal conv for one image row (block = row y).
__device__ __forceinline__ void ush_stage(
    const float* __restrict__ un, const float* sA, const float* skx,
    const float* sinx, const float* siny, float* sbuf,
    int bid, int t, bool first)
{
    if (bid >= H_) return;
    const int y = bid;
    float* sv = sbuf;            // [C_][W_]  (reused as qbuf)
    float* pp = sbuf + C_*W_;    // [C_][PPW] padded softmax rows

    if (!first) {
        #pragma unroll
        for (int r = 0; r < 6; r++) {
            int idx = t + r*NTHR;
            if (idx < C_*W_) {
                int c = idx >> 7, x = idx & 127;
                sv[idx] = __ldcv(&g_s[c*N_ + y*W_ + x]) * (sinx[x] * siny[y]);
            }
        }
    }
    // zero conv pads: [0,RAD) and [RAD+W_, PPW) of each padded row
    #pragma unroll
    for (int r = 0; r < 2; r++) {
        int idx = t + r*NTHR;
        if (idx < C_*(PPW - W_)) {
            int c = idx / (PPW - W_), k = idx % (PPW - W_);
            pp[c*PPW + (k < RAD ? k : W_ + k)] = 0.f;
        }
    }
    __syncthreads();

    // update matvec: thread (x, g) computes q for its 5-6 channels
    const int x = t & 127;
    const int g = t >> 7;
    const int c0 = grp_c0(g), ln = grp_len(g);
    float q[6];
    #pragma unroll 6
    for (int ci = 0; ci < 6; ci++) {
        if (ci >= ln) break;
        int c = c0 + ci;
        float acc = un[(y*W_ + x)*C_ + c];
        if (!first) {
            #pragma unroll
            for (int cp = 0; cp < C_; cp++)
                acc -= sA[c*C_ + cp] * sv[cp*W_ + x];
        }
        q[ci] = acc;
    }
    __syncthreads();               // all sv reads done before qbuf overwrite
    #pragma unroll 6
    for (int ci = 0; ci < 6; ci++) {
        if (ci >= ln) break;
        sv[(c0 + ci)*W_ + x] = q[ci];
    }
    __syncthreads();

    // softmax per pixel (128 threads)
    if (t < W_) {
        float v[C_];
        float m = -1e30f;
        #pragma unroll
        for (int c = 0; c < C_; c++) { v[c] = sv[c*W_ + t]; m = fmaxf(m, v[c]); }
        float s = 0.f;
        #pragma unroll
        for (int c = 0; c < C_; c++) { v[c] = expf(v[c] - m); s += v[c]; }
        float inv = 1.0f / s;
        #pragma unroll
        for (int c = 0; c < C_; c++) pp[c*PPW + RAD + t] = v[c] * inv;
    }
    __syncthreads();

    // horizontal conv, register-tiled: thread = (c, 6-wide x group)
    if (t < C_*22) {
        int c  = t / 22;
        int x0 = (t % 22) * 6;
        const float* p = pp + c*PPW + x0;    // out(x)=sum_j kx[j]*pp[x+j]
        float acc[6] = {0.f,0.f,0.f,0.f,0.f,0.f};
        #pragma unroll
        for (int i = 0; i < TAPS + 5; i++) {
            float v = p[i];
            #pragma unroll
            for (int r = 0; r < 6; r++) {
                int j = i - r;
                if (j >= 0 && j < TAPS) acc[r] += skx[j] * v;
            }
        }
        #pragma unroll
        for (int r = 0; r < 6; r++)
            if (x0 + r < W_) g_tmp[c*N_ + y*W_ + x0 + r] = acc[r];
    }
}

// Vertical conv: unit = (class, 32-wide x tile) = exactly 84 units, <=1 per block.
__device__ __forceinline__ void vstage(const float* skx, float* sbuf, int bid, int t)
{
    if (bid >= C_*4) return;
    const int c  = bid >> 2;
    const int x0 = (bid & 3) << 5;
    // load 128 padded rows x 32 cols
    #pragma unroll
    for (int r = 0; r < 8; r++) {
        int idx = t + r*NTHR;
        int yy = idx >> 5, xx = idx & 31;
        int yv = yy - RAD;
        sbuf[idx] = (yv >= 0 && yv < H_) ? __ldcv(&g_tmp[c*N_ + yv*W_ + x0 + xx]) : 0.f;
    }
    __syncthreads();
    // outputs: 16 y-groups (6 rows each) x 32 cols = 512 threads exactly
    const int xx = t & 31;
    const int y0 = (t >> 5) * 6;
    const float* base = sbuf + y0*32 + xx;   // out(y)=sum_j ky[j]*row[y+j]
    float acc[6] = {0.f,0.f,0.f,0.f,0.f,0.f};
    #pragma unroll
    for (int i = 0; i < TAPS + 5; i++) {
        float v = base[i*32];
        #pragma unroll
        for (int r = 0; r < 6; r++) {
            int j = i - r;
            if (j >= 0 && j < TAPS) acc[r] += skx[j] * v;
        }
    }
    #pragma unroll
    for (int r = 0; r < 6; r++)
        g_s[c*N_ + (y0 + r)*W_ + x0 + xx] = acc[r];
}

// Final update: q = u - A*(s/norm), write out in (1, W, H, C) layout.
__device__ __forceinline__ void final_stage(
    const float* __restrict__ un, float* __restrict__ out,
    const float* sA, const float* sinx, const float* siny,
    float* sbuf, int bid, int t)
{
    if (bid >= H_) return;
    const int y = bid;
    float* sv = sbuf;
    #pragma unroll
    for (int r = 0; r < 6; r++) {
        int idx = t + r*NTHR;
        if (idx < C_*W_) {
            int c = idx >> 7, x = idx & 127;
            sv[idx] = __ldcv(&g_s[c*N_ + y*W_ + x]) * (sinx[x] * siny[y]);
        }
    }
    __syncthreads();
    const int x = t & 127;
    const int g = t >> 7;
    const int c0 = grp_c0(g), ln = grp_len(g);
    #pragma unroll 6
    for (int ci = 0; ci < 6; ci++) {
        if (ci >= ln) break;
        int c = c0 + ci;
        float acc = un[(y*W_ + x)*C_ + c];
        #pragma unroll
        for (int cp = 0; cp < C_; cp++)
            acc -= sA[c*C_ + cp] * sv[cp*W_ + x];
        out[(x*H_ + y)*C_ + c] = acc;      // out[0, w, h, c]
    }
}

__global__ __launch_bounds__(NTHR, 1)
void crf_persistent(const float* __restrict__ un,
                    const float* __restrict__ ws,
                    const float* __restrict__ wb,
                    const float* __restrict__ compat,
                    float* __restrict__ out)
{
    __shared__ float sA[C_*C_];
    __shared__ float skx[TAPS];
    __shared__ float sinx[W_];
    __shared__ float siny[H_];
    __shared__ float sbuf[C_*W_ + C_*PPW];   // 2688 + 3528 floats (vstage uses 4096)

    const int t   = threadIdx.x;
    const int bid = blockIdx.x;

    // ---- per-block init (redundant across blocks; cheap) ----
    if (t < TAPS) skx[t] = expf(-(float)((t-RAD)*(t-RAD)) / 18.0f);
    __syncthreads();
    if (t < W_) {
        float s = 0.f;
        #pragma unroll
        for (int j = 0; j < TAPS; j++) {
            int xp = t + j - RAD;
            if (xp >= 0 && xp < W_) s += skx[j];
        }
        sinx[t] = 1.0f / s;
    }
    if (t >= 128 && t < 128 + H_) {
        int y = t - 128;
        float s = 0.f;
        #pragma unroll
        for (int j = 0; j < TAPS; j++) {
            int yp = y + j - RAD;
            if (yp >= 0 && yp < H_) s += skx[j];
        }
        siny[y] = 1.0f / s;
    }
    for (int idx = t; idx < C_*C_; idx += NTHR) {
        int i = idx / C_, j = idx % C_;
        float a = 0.f;
        #pragma unroll
        for (int k = 0; k < C_; k++)
            a += compat[i*C_ + k] * (ws[k*C_ + j] + wb[k*C_ + j]);
        sA[idx] = a;   // A = compat @ (Ws + Wb); bilateral path is dead (source bug)
    }
    __syncthreads();

    ush_stage(un, sA, skx, sinx, siny, sbuf, bid, t, true);   // softmax(u) + hconv
    grid_bar();
    for (int it = 0; it < 5; it++) {
        vstage(skx, sbuf, bid, t);
        grid_bar();
        if (it < 4) {
            ush_stage(un, sA, skx, sinx, siny, sbuf, bid, t, false);
            grid_bar();
        } else {
            final_stage(un, out, sA, sinx, siny, sbuf, bid, t);
        }
    }
}

extern "C" void kernel_launch(void* const* d_in, const int* in_sizes, int n_in,
                              void* d_out, int out_size) {
    const float* un     = (const float*)d_in[0];
    // d_in[1] = rgb : provably unused (bilateral output discarded by replicated source bug)
    const float* ws     = (const float*)d_in[2];
    const float* wb     = (const float*)d_in[3];
    const float* compat = (const float*)d_in[4];
    float* out = (float*)d_out;

    crf_persistent<<<GRID, NTHR>>>(un, ws, wb, compat, out);
}